// round 1
// baseline (speedup 1.0000x reference)
#include <cuda_runtime.h>
#include <cstdint>
#include <cstddef>

// Problem constants (fixed by the dataset)
#define Bn   8
#define Tn   128
#define Un   64
#define U1n  65          // U+1
#define Vn   1024
// blank = V-1 (last class)

// Scratch: per-(b,t,u) log-probs surviving the softmax reduction.
__device__ float g_blank[Bn * Tn * U1n];   // lp[..., blank]          (b,t,u<=U)
__device__ float g_emit [Bn * Tn * Un];    // lp[..., targets[b,u]]   (b,t,u<U)

__device__ __forceinline__ float neg_inf() { return __int_as_float(0xff800000u); }

// a,b never both -inf at call sites.
__device__ __forceinline__ float logaddexpf_(float a, float b) {
    float mx = fmaxf(a, b);
    float mn = fminf(a, b);
    return mx + __logf(1.0f + __expf(mn - mx));
}

// ---------------------------------------------------------------------------
// Kernel 1: per-row log-sum-exp over V=1024; one warp per (b,t,u) row.
// Each thread loads 8 float4 (32 scalars), two-pass in registers, warp
// butterfly combine of (max, sumexp). Rows outside [0,T_l) x [0,U_l] skipped
// entirely -> real DRAM traffic savings (~43%).
// ---------------------------------------------------------------------------
__global__ void __launch_bounds__(256) lse_kernel(
    const float* __restrict__ logits,
    const int*   __restrict__ targets,
    const int*   __restrict__ logit_lengths,
    const int*   __restrict__ target_lengths)
{
    int warp = (int)((blockIdx.x * 256u + threadIdx.x) >> 5);
    int lane = threadIdx.x & 31;
    if (warp >= Bn * Tn * U1n) return;

    int b   = warp / (Tn * U1n);
    int rem = warp - b * (Tn * U1n);
    int t   = rem / U1n;
    int u   = rem - t * U1n;

    int Tl = logit_lengths[b];
    int Ul = target_lengths[b];
    if (t >= Tl || u > Ul) return;   // never read by the DP

    const float4* row = reinterpret_cast<const float4*>(logits) + (size_t)warp * (Vn / 4);
    float4 v[8];
#pragma unroll
    for (int j = 0; j < 8; j++) v[j] = row[j * 32 + lane];

    float m = v[0].x;
#pragma unroll
    for (int j = 0; j < 8; j++) {
        m = fmaxf(m, v[j].x); m = fmaxf(m, v[j].y);
        m = fmaxf(m, v[j].z); m = fmaxf(m, v[j].w);
    }
    float s = 0.0f;
#pragma unroll
    for (int j = 0; j < 8; j++) {
        s += __expf(v[j].x - m); s += __expf(v[j].y - m);
        s += __expf(v[j].z - m); s += __expf(v[j].w - m);
    }

    // blank class = V-1: lives in v[7].w of lane 31; grab before reduction.
    float blankv = __shfl_sync(0xffffffffu, v[7].w, 31);

    // Butterfly combine of (m, s)
#pragma unroll
    for (int off = 16; off; off >>= 1) {
        float om = __shfl_xor_sync(0xffffffffu, m, off);
        float os = __shfl_xor_sync(0xffffffffu, s, off);
        float nm = fmaxf(m, om);
        s = s * __expf(m - nm) + os * __expf(om - nm);
        m = nm;
    }
    float lse = m + __logf(s);

    if (lane == 0) {
        g_blank[warp] = blankv - lse;
        if (u < Ul) {
            int tgt = targets[b * Un + u];
            // L1/L2 hit: this warp just streamed the row.
            g_emit[(b * Tn + t) * Un + u] = logits[(size_t)warp * Vn + tgt] - lse;
        }
    }
}

// ---------------------------------------------------------------------------
// Kernel 2: anti-diagonal wavefront DP. One CTA per batch element.
// alpha[t][u] = logaddexp(alpha[t-1][u] + blank[t-1][u],
//                         alpha[t][u-1] + emit[t][u-1]),  alpha[0][0]=0.
// Both deps live on diagonal d-1 -> ping-pong diagonal buffers, 1 sync/diag.
// SMEM strides: blank uses 66 (stride-65 per-thread addr => conflict-free;
// the natural 65 would be a 65-way same-bank conflict), emit uses 64
// (stride-63, also conflict-free).
// ---------------------------------------------------------------------------
__global__ void __launch_bounds__(128) dp_kernel(
    const int* __restrict__ logit_lengths,
    const int* __restrict__ target_lengths,
    float*     __restrict__ out)
{
    int b   = blockIdx.x;
    int tid = threadIdx.x;
    int Tl  = logit_lengths[b];
    int Ul  = target_lengths[b];

    extern __shared__ float sh[];
    float* s_blank = sh;                       // Tn * 66
    float* s_emit  = sh + Tn * 66;             // Tn * 64
    float* d0      = s_emit + Tn * 64;         // 66
    float* d1      = d0 + 66;                  // 66

    // Preload the needed region of lp arrays into SMEM (coalesced).
    for (int t = 0; t < Tl; t++) {
        const float* gb = g_blank + (b * Tn + t) * U1n;
        const float* ge = g_emit  + (b * Tn + t) * Un;
        for (int uu = tid; uu <= Ul; uu += 128) s_blank[t * 66 + uu] = gb[uu];
        for (int uu = tid; uu <  Ul; uu += 128) s_emit [t * 64 + uu] = ge[uu];
    }
    __syncthreads();

    float* prev = d0;
    float* cur  = d1;
    int t_last = Tl - 1;
    int u_last = Ul;
    int d_end  = t_last + u_last;
    int u = tid;

    for (int d = 0; d <= d_end; d++) {
        if (u <= Ul && u <= d && (d - u) <= t_last) {
            int t = d - u;
            float a;
            if (d == 0) {
                a = 0.0f;
            } else {
                float va = (t >= 1) ? prev[u]     + s_blank[(t - 1) * 66 + u] : neg_inf();
                float vb = (u >= 1) ? prev[u - 1] + s_emit [t * 64 + (u - 1)] : neg_inf();
                a = logaddexpf_(va, vb);
            }
            cur[u] = a;
            if (d == d_end && u == u_last) {
                out[b] = -(a + s_blank[t_last * 66 + u_last]);
            }
        }
        __syncthreads();
        float* tmp = prev; prev = cur; cur = tmp;
    }
}

// ---------------------------------------------------------------------------
extern "C" void kernel_launch(void* const* d_in, const int* in_sizes, int n_in,
                              void* d_out, int out_size)
{
    const float* logits         = (const float*)d_in[0];
    const int*   targets        = (const int*)  d_in[1];
    const int*   logit_lengths  = (const int*)  d_in[2];
    const int*   target_lengths = (const int*)  d_in[3];
    float*       out            = (float*)      d_out;

    const int smem_bytes = (Tn * 66 + Tn * 64 + 2 * 66) * (int)sizeof(float); // 67088
    cudaFuncSetAttribute(dp_kernel, cudaFuncAttributeMaxDynamicSharedMemorySize, smem_bytes);

    int rows   = Bn * Tn * U1n;            // 66560 warps
    int blocks = (rows * 32 + 255) / 256;  // 8320 blocks, 8 rows each

    lse_kernel<<<blocks, 256>>>(logits, targets, logit_lengths, target_lengths);
    dp_kernel<<<Bn, 128, smem_bytes>>>(logit_lengths, target_lengths, out);
}

// round 5
// speedup vs baseline: 2.4476x; 2.4476x over previous
#include <cuda_runtime.h>
#include <cstdint>
#include <cstddef>

// Problem constants (fixed by the dataset)
#define Bn   8
#define Tn   128
#define Un   64
#define U1n  65          // U+1
#define Vn   1024
// blank = V-1 (last class)

// Scratch: per-(b,t,u) log-probs surviving the softmax reduction.
__device__ float g_blank[Bn * Tn * U1n];   // lp[..., blank]          (b,t,u<=U)
__device__ float g_emit [Bn * Tn * Un];    // lp[..., targets[b,u]]   (b,t,u<U)

__device__ __forceinline__ float neg_inf() { return __int_as_float(0xff800000u); }

// Guarded logaddexp: returns -inf if both inputs are -inf (never NaN).
__device__ __forceinline__ float lae(float va, float vb) {
    float mx = fmaxf(va, vb);
    float mn = fminf(va, vb);
    float r  = mx + __logf(1.0f + __expf(mn - mx));
    return (mx == neg_inf()) ? neg_inf() : r;
}

// ---------------------------------------------------------------------------
// Kernel 1: per-row log-sum-exp over V=1024; one warp per (b,t,u) row.
// Rows outside [0,T_l) x [0,U_l] skipped entirely (~43% DRAM saved).
// ---------------------------------------------------------------------------
__global__ void __launch_bounds__(256) lse_kernel(
    const float* __restrict__ logits,
    const int*   __restrict__ targets,
    const int*   __restrict__ logit_lengths,
    const int*   __restrict__ target_lengths)
{
    int warp = (int)((blockIdx.x * 256u + threadIdx.x) >> 5);
    int lane = threadIdx.x & 31;
    if (warp >= Bn * Tn * U1n) return;

    int b   = warp / (Tn * U1n);
    int rem = warp - b * (Tn * U1n);
    int t   = rem / U1n;
    int u   = rem - t * U1n;

    int Tl = logit_lengths[b];
    int Ul = target_lengths[b];
    if (t >= Tl || u > Ul) return;   // never read by the DP

    const float4* row = reinterpret_cast<const float4*>(logits) + (size_t)warp * (Vn / 4);
    float4 v[8];
#pragma unroll
    for (int j = 0; j < 8; j++) v[j] = row[j * 32 + lane];

    float m = v[0].x;
#pragma unroll
    for (int j = 0; j < 8; j++) {
        m = fmaxf(m, v[j].x); m = fmaxf(m, v[j].y);
        m = fmaxf(m, v[j].z); m = fmaxf(m, v[j].w);
    }
    float s = 0.0f;
#pragma unroll
    for (int j = 0; j < 8; j++) {
        s += __expf(v[j].x - m); s += __expf(v[j].y - m);
        s += __expf(v[j].z - m); s += __expf(v[j].w - m);
    }

    // blank class = V-1: lives in v[7].w of lane 31; grab before reduction.
    float blankv = __shfl_sync(0xffffffffu, v[7].w, 31);

    // Butterfly combine of (m, s)
#pragma unroll
    for (int off = 16; off; off >>= 1) {
        float om = __shfl_xor_sync(0xffffffffu, m, off);
        float os = __shfl_xor_sync(0xffffffffu, s, off);
        float nm = fmaxf(m, om);
        s = s * __expf(m - nm) + os * __expf(om - nm);
        m = nm;
    }
    float lse = m + __logf(s);

    if (lane == 0) {
        g_blank[warp] = blankv - lse;
        if (u < Ul) {
            int tgt = targets[b * Un + u];
            g_emit[(b * Tn + t) * Un + u] = logits[(size_t)warp * Vn + tgt] - lse;
        }
    }
}

// ---------------------------------------------------------------------------
// Kernel 2: anti-diagonal wavefront DP, ONE WARP per batch element.
// Lane l owns columns u = l (slot0) and u = l+32 (slot1); lane 31 additionally
// owns u = 64 (slot2). Diagonal d-1 -> d dependency carried by one rotating
// __shfl_sync per slot; no __syncthreads in the loop.
// Preload done by all 128 threads (flat, coalesced, high MLP); warps 1-3 exit.
// SMEM strides: blank 66 (addr step -65 == -1 mod 32, conflict-free),
//               emit 64 (addr step -63 == +1 mod 32, conflict-free).
// ---------------------------------------------------------------------------
__global__ void __launch_bounds__(128) dp_kernel(
    const int* __restrict__ logit_lengths,
    const int* __restrict__ target_lengths,
    float*     __restrict__ out)
{
    int b    = blockIdx.x;
    int tid  = threadIdx.x;
    int lane = tid & 31;
    int Tl   = logit_lengths[b];
    int Ul   = target_lengths[b];

    extern __shared__ float sh[];
    float* s_blank = sh;                // Tn * 66
    float* s_emit  = sh + Tn * 66;      // Tn * 64

    // Flat coalesced preload: every thread issues ~65 independent LDGs.
    int nblk = Tl * U1n;
    const float* gb = g_blank + b * Tn * U1n;
    for (int i = tid; i < nblk; i += 128) {
        int t  = i / U1n;
        int uu = i - t * U1n;
        s_blank[t * 66 + uu] = gb[i];
    }
    int nem = Tl * Un;
    const float* ge = g_emit + b * Tn * Un;
    for (int i = tid; i < nem; i += 128) {
        s_emit[i] = ge[i];              // identical stride-64 layout
    }
    __syncthreads();
    if (tid >= 32) return;              // warp 0 runs the DP alone

    const float NEG = neg_inf();
    const int u0 = lane;
    const int u1 = lane + 32;
    const int t_last = Tl - 1;
    const int u_last = Ul;
    const int d_end  = t_last + u_last;
    const int um1_0  = (lane == 0) ? 0 : lane - 1;   // clamped u0-1

    float p0 = NEG, p1 = NEG, p2 = NEG;  // alpha on previous diagonal

    for (int d = 0; d <= d_end; d++) {
        // Rotating shuffle: lane l receives lane (l-1)'s value; lane 0 gets lane 31's.
        float s0 = __shfl_sync(0xffffffffu, p0, (lane + 31) & 31);
        float s1 = __shfl_sync(0xffffffffu, p1, (lane + 31) & 31);
        float nb0 = s0;                              // alpha[t][u0-1]
        float nb1 = (lane == 0) ? s0 : s1;           // u1=32 neighbor u=31 = lane31 slot0
        float nb2 = p1;                              // u=64 neighbor u=63 = own slot1

        // ---- slot0: u = lane ----
        int  t0  = d - u0;
        bool c0  = (u0 <= u_last) && (t0 >= 0) && (t0 <= t_last);
        int  t0b = min(max(t0 - 1, 0), t_last);
        int  t0c = min(max(t0,     0), t_last);
        float blk0 = s_blank[t0b * 66 + u0];
        float emt0 = s_emit [t0c * 64 + um1_0];
        float va0 = (c0 && t0 >= 1) ? p0  + blk0 : NEG;
        float vb0 = (c0 && u0 >= 1) ? nb0 + emt0 : NEG;
        float a0 = lae(va0, vb0);
        if (u0 == 0 && t0 == 0) a0 = 0.0f;           // alpha[0][0] = 0

        // ---- slot1: u = lane+32 ----
        int  t1  = d - u1;
        bool c1  = (u1 <= u_last) && (t1 >= 0) && (t1 <= t_last);
        int  t1b = min(max(t1 - 1, 0), t_last);
        int  t1c = min(max(t1,     0), t_last);
        float blk1 = s_blank[t1b * 66 + u1];
        float emt1 = s_emit [t1c * 64 + (u1 - 1)];
        float va1 = (c1 && t1 >= 1) ? p1  + blk1 : NEG;
        float vb1 = c1              ? nb1 + emt1 : NEG;   // u1 >= 32 > 0 always
        float a1 = lae(va1, vb1);

        // ---- slot2: u = 64 (meaningful on lane 31 only; uniform otherwise) ----
        int  t2  = d - 64;
        bool c2  = (64 <= u_last) && (t2 >= 0) && (t2 <= t_last);
        int  t2b = min(max(t2 - 1, 0), t_last);
        int  t2c = min(max(t2,     0), t_last);
        float blk2 = s_blank[t2b * 66 + 64];
        float emt2 = s_emit [t2c * 64 + 63];
        float va2 = (c2 && t2 >= 1) ? p2  + blk2 : NEG;
        float vb2 = c2              ? nb2 + emt2 : NEG;
        float a2 = lae(va2, vb2);

        p0 = a0; p1 = a1; p2 = a2;
    }

    // Extract alpha[t_last][u_last] from the final diagonal.
    float af;
    if (u_last == 64)      af = __shfl_sync(0xffffffffu, p2, 31);
    else if (u_last >= 32) af = __shfl_sync(0xffffffffu, p1, u_last - 32);
    else                   af = __shfl_sync(0xffffffffu, p0, u_last);

    if (lane == 0) {
        out[b] = -(af + s_blank[t_last * 66 + u_last]);
    }
}

// ---------------------------------------------------------------------------
extern "C" void kernel_launch(void* const* d_in, const int* in_sizes, int n_in,
                              void* d_out, int out_size)
{
    const float* logits         = (const float*)d_in[0];
    const int*   targets        = (const int*)  d_in[1];
    const int*   logit_lengths  = (const int*)  d_in[2];
    const int*   target_lengths = (const int*)  d_in[3];
    float*       out            = (float*)      d_out;

    const int smem_bytes = (Tn * 66 + Tn * 64) * (int)sizeof(float); // 66560 B
    static int attr_set = 0;
    if (!attr_set) {
        cudaFuncSetAttribute(dp_kernel, cudaFuncAttributeMaxDynamicSharedMemorySize, smem_bytes);
        attr_set = 1;
    }

    int rows   = Bn * Tn * U1n;            // 66560 rows -> one warp each
    int blocks = (rows * 32 + 255) / 256;  // 8320 blocks

    lse_kernel<<<blocks, 256>>>(logits, targets, logit_lengths, target_lengths);
    dp_kernel<<<Bn, 128, smem_bytes>>>(logit_lengths, target_lengths, out);
}

// round 8
// speedup vs baseline: 2.6999x; 1.1031x over previous
#include <cuda_runtime.h>
#include <cstdint>
#include <cstddef>

// Problem constants (fixed by the dataset)
#define Bn   8
#define Tn   128
#define Un   64
#define U1n  65          // U+1
#define Vn   1024
// blank = V-1 (last class)

// Scratch: per-(b,t,u) log-probs surviving the softmax reduction.
__device__ float g_blank[Bn * Tn * U1n];   // lp[..., blank]          (b,t,u<=U)
__device__ float g_emit [Bn * Tn * Un];    // lp[..., targets[b,u]]   (b,t,u<U)

__device__ __forceinline__ float neg_inf() { return __int_as_float(0xff800000u); }

// NaN-free logaddexp without a predicate guard:
//   both -inf: mn-mx = NaN, fmaxf(NaN,-30) = -30 -> result = -inf + eps = -inf.
//   one  -inf: z clamps to -30 -> result = mx + 9e-14 (abs err < 1e-13).
__device__ __forceinline__ float lae(float va, float vb) {
    float mx = fmaxf(va, vb);
    float mn = fminf(va, vb);
    float z  = fmaxf(mn - mx, -30.0f);
    return mx + __logf(1.0f + __expf(z));
}

// ---------------------------------------------------------------------------
// Kernel 1: per-row log-sum-exp over V=1024; one warp per (b,t,u) row.
// Rows outside [0,T_l) x [0,U_l] skipped entirely (~43% DRAM saved).
// Measured at the LTS/DRAM cap (~6.5 TB/s) -> leave unchanged.
// ---------------------------------------------------------------------------
__global__ void __launch_bounds__(256) lse_kernel(
    const float* __restrict__ logits,
    const int*   __restrict__ targets,
    const int*   __restrict__ logit_lengths,
    const int*   __restrict__ target_lengths)
{
    int warp = (int)((blockIdx.x * 256u + threadIdx.x) >> 5);
    int lane = threadIdx.x & 31;
    if (warp >= Bn * Tn * U1n) return;

    int b   = warp / (Tn * U1n);
    int rem = warp - b * (Tn * U1n);
    int t   = rem / U1n;
    int u   = rem - t * U1n;

    int Tl = logit_lengths[b];
    int Ul = target_lengths[b];
    if (t >= Tl || u > Ul) return;   // never read by the DP

    const float4* row = reinterpret_cast<const float4*>(logits) + (size_t)warp * (Vn / 4);
    float4 v[8];
#pragma unroll
    for (int j = 0; j < 8; j++) v[j] = row[j * 32 + lane];

    float m = v[0].x;
#pragma unroll
    for (int j = 0; j < 8; j++) {
        m = fmaxf(m, v[j].x); m = fmaxf(m, v[j].y);
        m = fmaxf(m, v[j].z); m = fmaxf(m, v[j].w);
    }
    float s = 0.0f;
#pragma unroll
    for (int j = 0; j < 8; j++) {
        s += __expf(v[j].x - m); s += __expf(v[j].y - m);
        s += __expf(v[j].z - m); s += __expf(v[j].w - m);
    }

    // blank class = V-1: lives in v[7].w of lane 31; grab before reduction.
    float blankv = __shfl_sync(0xffffffffu, v[7].w, 31);

    // Butterfly combine of (m, s)
#pragma unroll
    for (int off = 16; off; off >>= 1) {
        float om = __shfl_xor_sync(0xffffffffu, m, off);
        float os = __shfl_xor_sync(0xffffffffu, s, off);
        float nm = fmaxf(m, om);
        s = s * __expf(m - nm) + os * __expf(om - nm);
        m = nm;
    }
    float lse = m + __logf(s);

    if (lane == 0) {
        g_blank[warp] = blankv - lse;
        if (u < Ul) {
            int tgt = targets[b * Un + u];
            g_emit[(b * Tn + t) * Un + u] = logits[(size_t)warp * Vn + tgt] - lse;
        }
    }
}

// ---------------------------------------------------------------------------
// Kernel 2: anti-diagonal wavefront DP, one warp per batch.
// Lane l owns u = l (slot0), u = l+32 (slot1); u = 64 is slot2 (lane31's
// value is the real one; other lanes compute harmless garbage).
//
// All boundary handling is by CONSTRUCTION, not predicates:
//  - SMEM padded 64 rows below/above and zero-filled, so every load in every
//    iteration is in-bounds and finite.
//  - alpha registers start at -inf; invalid cells stay -inf because a valid
//    cell's parents always have t' <= t (spurious values never flow back).
//  - only lane0's "no left neighbor" needs one select.
// Addresses advance by constant strides (+66/+64 floats per diagonal): zero
// per-iteration address arithmetic beyond 6 IADDs.
// Bank math: blank addr = C - 65*u == -u (mod 32): conflict-free.
//            emit  addr = C - 63*u == +u (mod 32): conflict-free.
// ---------------------------------------------------------------------------
#define PAD_LO   64
#define SROWS    256                    // PAD_LO + Tn + head-room (t up to 191)
#define BLK_F    (SROWS * 66)           // 16896 floats
#define EMT_F    (SROWS * 64)           // 16384 floats
#define TOT_F    (BLK_F + EMT_F)        // 33280 floats = 133120 B

__global__ void __launch_bounds__(128) dp_kernel(
    const int* __restrict__ logit_lengths,
    const int* __restrict__ target_lengths,
    float*     __restrict__ out)
{
    int b    = blockIdx.x;
    int tid  = threadIdx.x;
    int lane = tid & 31;
    int Tl   = logit_lengths[b];
    int Ul   = target_lengths[b];

    extern __shared__ float sh[];
    float* s_blank0 = sh + PAD_LO * 66;              // row-0 of blank
    float* s_emit0  = sh + BLK_F + PAD_LO * 64;      // row-0 of emit

    // Zero the whole padded region (vectorized), then overwrite live rows.
    {
        float4* sh4 = reinterpret_cast<float4*>(sh);
        const float4 z4 = make_float4(0.f, 0.f, 0.f, 0.f);
        for (int i = tid; i < TOT_F / 4; i += 128) sh4[i] = z4;
    }
    __syncthreads();

    // Flat coalesced preload of the live region.
    {
        int nblk = Tl * U1n;
        const float* gb = g_blank + b * Tn * U1n;
        for (int i = tid; i < nblk; i += 128) {
            int t  = i / U1n;
            int uu = i - t * U1n;
            s_blank0[t * 66 + uu] = gb[i];
        }
        int nem = Tl * Un;
        const float* ge = g_emit + b * Tn * Un;
        for (int i = tid; i < nem; i += 128) {
            s_emit0[i] = ge[i];          // same stride-64 layout
        }
    }
    __syncthreads();
    if (tid >= 32) return;               // warp 0 runs the DP alone

    const float NEG = neg_inf();
    const int u0 = lane;
    const int u1 = lane + 32;
    const int t_last = Tl - 1;
    const int u_last = Ul;
    const int d_end  = t_last + u_last;

    // Incremental SMEM pointers, positioned for d = 1.
    const float* pb0 = s_blank0 + (0 - u0) * 66 + u0;          // row d-u0-1
    const float* pe0 = s_emit0  + (1 - u0) * 64 + (u0 - 1);    // row d-u0, col u0-1
    const float* pb1 = s_blank0 + (0 - u1) * 66 + u1;
    const float* pe1 = s_emit0  + (1 - u1) * 64 + (u1 - 1);
    const float* pb2 = s_blank0 + (0 - 64) * 66 + 64;
    const float* pe2 = s_emit0  + (1 - 64) * 64 + 63;

    // Diagonal d = 0: only cell (0,0) = 0.
    float p0 = (lane == 0) ? 0.0f : NEG;
    float p1 = NEG, p2 = NEG;

    const int src = (lane + 31) & 31;
    const bool l0 = (lane == 0);

#pragma unroll 2
    for (int d = 1; d <= d_end; d++) {
        float s0 = __shfl_sync(0xffffffffu, p0, src);
        float s1 = __shfl_sync(0xffffffffu, p1, src);
        float nb0 = l0 ? NEG : s0;       // u=0 has no left neighbor
        float nb1 = l0 ? s0  : s1;       // u1=32's left neighbor is lane31 slot0
        float nb2 = p1;                  // u=64's left neighbor is own slot1 (lane31)

        float blk0 = *pb0; pb0 += 66;
        float emt0 = *pe0; pe0 += 64;
        float blk1 = *pb1; pb1 += 66;
        float emt1 = *pe1; pe1 += 64;
        float blk2 = *pb2; pb2 += 66;
        float emt2 = *pe2; pe2 += 64;

        p0 = lae(p0 + blk0, nb0 + emt0);
        p1 = lae(p1 + blk1, nb1 + emt1);
        p2 = lae(p2 + blk2, nb2 + emt2);
    }

    // Extract alpha[t_last][u_last] from the final diagonal.
    float af;
    if (u_last == 64)      af = __shfl_sync(0xffffffffu, p2, 31);
    else if (u_last >= 32) af = __shfl_sync(0xffffffffu, p1, u_last - 32);
    else                   af = __shfl_sync(0xffffffffu, p0, u_last);

    if (lane == 0) {
        out[b] = -(af + s_blank0[t_last * 66 + u_last]);
    }
}

// ---------------------------------------------------------------------------
extern "C" void kernel_launch(void* const* d_in, const int* in_sizes, int n_in,
                              void* d_out, int out_size)
{
    const float* logits         = (const float*)d_in[0];
    const int*   targets        = (const int*)  d_in[1];
    const int*   logit_lengths  = (const int*)  d_in[2];
    const int*   target_lengths = (const int*)  d_in[3];
    float*       out            = (float*)      d_out;

    const int smem_bytes = TOT_F * (int)sizeof(float);   // 133120 B
    static int attr_set = 0;
    if (!attr_set) {
        cudaFuncSetAttribute(dp_kernel, cudaFuncAttributeMaxDynamicSharedMemorySize, smem_bytes);
        attr_set = 1;
    }

    int rows   = Bn * Tn * U1n;            // 66560 rows -> one warp each
    int blocks = (rows * 32 + 255) / 256;  // 8320 blocks

    lse_kernel<<<blocks, 256>>>(logits, targets, logit_lengths, target_lengths);
    dp_kernel<<<Bn, 128, smem_bytes>>>(logit_lengths, target_lengths, out);
}

// round 9
// speedup vs baseline: 2.7916x; 1.0339x over previous
#include <cuda_runtime.h>
#include <cstdint>
#include <cstddef>

// Problem constants (fixed by the dataset)
#define Bn   8
#define Tn   128
#define Un   64
#define U1n  65          // U+1
#define Vn   1024
// blank = V-1 (last class)

#define LOG2E 1.4426950408889634f
#define LN2   0.6931471805599453f

// Scratch: per-(b,t,u) log-probs (in BASE-2 log domain) after softmax reduction.
__device__ float g_blank[Bn * Tn * U1n];   // lp2[..., blank]          (b,t,u<=U)
__device__ float g_emit [Bn * Tn * Un];    // lp2[..., targets[b,u]]   (b,t,u<U)

__device__ __forceinline__ float neg_inf() { return __int_as_float(0xff800000u); }

// Base-2 logaddexp, NaN-free without predicates:
//   both -inf: mn-mx = NaN, fmaxf(NaN,-45) = -45 -> mx + 2^-45 = -inf.
//   one  -inf: z clamps to -45 -> abs err ~ 4e-14.
__device__ __forceinline__ float lae2(float va, float vb) {
    float mx = fmaxf(va, vb);
    float mn = fminf(va, vb);
    float z  = fmaxf(mn - mx, -45.0f);
    return mx + __log2f(1.0f + exp2f(z));
}

// ---------------------------------------------------------------------------
// Kernel 1: per-row log-sum-exp over V=1024; one warp per (b,t,u) row.
// Rows outside [0,T_l) x [0,U_l] skipped entirely (~43% DRAM saved).
// Measured at the LTS/DRAM cap (~6.5 TB/s). Outputs scaled by log2(e) so the
// DP can run fully in base-2.
// ---------------------------------------------------------------------------
__global__ void __launch_bounds__(256) lse_kernel(
    const float* __restrict__ logits,
    const int*   __restrict__ targets,
    const int*   __restrict__ logit_lengths,
    const int*   __restrict__ target_lengths)
{
    int warp = (int)((blockIdx.x * 256u + threadIdx.x) >> 5);
    int lane = threadIdx.x & 31;
    if (warp >= Bn * Tn * U1n) return;

    int b   = warp / (Tn * U1n);
    int rem = warp - b * (Tn * U1n);
    int t   = rem / U1n;
    int u   = rem - t * U1n;

    int Tl = logit_lengths[b];
    int Ul = target_lengths[b];
    if (t >= Tl || u > Ul) return;   // never read by the DP

    const float4* row = reinterpret_cast<const float4*>(logits) + (size_t)warp * (Vn / 4);
    float4 v[8];
#pragma unroll
    for (int j = 0; j < 8; j++) v[j] = row[j * 32 + lane];

    float m = v[0].x;
#pragma unroll
    for (int j = 0; j < 8; j++) {
        m = fmaxf(m, v[j].x); m = fmaxf(m, v[j].y);
        m = fmaxf(m, v[j].z); m = fmaxf(m, v[j].w);
    }
    float s = 0.0f;
#pragma unroll
    for (int j = 0; j < 8; j++) {
        s += __expf(v[j].x - m); s += __expf(v[j].y - m);
        s += __expf(v[j].z - m); s += __expf(v[j].w - m);
    }

    // blank class = V-1: lives in v[7].w of lane 31; grab before reduction.
    float blankv = __shfl_sync(0xffffffffu, v[7].w, 31);

    // Butterfly combine of (m, s)
#pragma unroll
    for (int off = 16; off; off >>= 1) {
        float om = __shfl_xor_sync(0xffffffffu, m, off);
        float os = __shfl_xor_sync(0xffffffffu, s, off);
        float nm = fmaxf(m, om);
        s = s * __expf(m - nm) + os * __expf(om - nm);
        m = nm;
    }
    float lse = m + __logf(s);

    if (lane == 0) {
        g_blank[warp] = (blankv - lse) * LOG2E;
        if (u < Ul) {
            int tgt = targets[b * Un + u];
            g_emit[(b * Tn + t) * Un + u] = (logits[(size_t)warp * Vn + tgt] - lse) * LOG2E;
        }
    }
}

// ---------------------------------------------------------------------------
// Kernel 2: anti-diagonal wavefront DP, one warp per batch, base-2 log domain.
// Lane l owns u = l (slot0), u = l+32 (slot1); u = 64 is slot2 (lane31 real).
// Boundary handling by construction (padded, zero-filled SMEM; -inf regs).
// SMEM loads for diagonal d+1 are prefetched into registers before the lae
// chain of diagonal d -> LDS latency fully hidden under the serial recurrence.
// Bank math: blank addr step == -u (mod 32), emit step == +u: conflict-free.
// ---------------------------------------------------------------------------
#define PAD_LO   64
#define SROWS    256                    // rows -64..191; max accessed row = 192-1 ok
#define BLK_F    (SROWS * 66)           // 16896 floats
#define EMT_F    (SROWS * 64)           // 16384 floats
#define TAIL_F   64                     // safety pad for the last prefetch
#define TOT_F    (BLK_F + EMT_F + TAIL_F)

__global__ void __launch_bounds__(128) dp_kernel(
    const int* __restrict__ logit_lengths,
    const int* __restrict__ target_lengths,
    float*     __restrict__ out)
{
    int b    = blockIdx.x;
    int tid  = threadIdx.x;
    int lane = tid & 31;
    int Tl   = logit_lengths[b];
    int Ul   = target_lengths[b];

    extern __shared__ float sh[];
    float* s_blank0 = sh + PAD_LO * 66;              // row-0 of blank
    float* s_emit0  = sh + BLK_F + PAD_LO * 64;      // row-0 of emit

    // Zero the whole padded region (vectorized), then overwrite live rows.
    {
        float4* sh4 = reinterpret_cast<float4*>(sh);
        const float4 z4 = make_float4(0.f, 0.f, 0.f, 0.f);
        for (int i = tid; i < TOT_F / 4; i += 128) sh4[i] = z4;
    }
    __syncthreads();

    // Flat coalesced preload of the live region.
    {
        int nblk = Tl * U1n;
        const float* gb = g_blank + b * Tn * U1n;
        for (int i = tid; i < nblk; i += 128) {
            int t  = i / U1n;
            int uu = i - t * U1n;
            s_blank0[t * 66 + uu] = gb[i];
        }
        int nem = Tl * Un;
        const float* ge = g_emit + b * Tn * Un;
        for (int i = tid; i < nem; i += 128) {
            s_emit0[i] = ge[i];          // same stride-64 layout
        }
    }
    __syncthreads();
    if (tid >= 32) return;               // warp 0 runs the DP alone

    const float NEG = neg_inf();
    const int u0 = lane;
    const int u1 = lane + 32;
    const int t_last = Tl - 1;
    const int u_last = Ul;
    const int d_end  = t_last + u_last;

    // Incremental SMEM pointers, positioned for d = 1.
    const float* pb0 = s_blank0 + (0 - u0) * 66 + u0;          // row d-u0-1
    const float* pe0 = s_emit0  + (1 - u0) * 64 + (u0 - 1);    // row d-u0, col u0-1
    const float* pb1 = s_blank0 + (0 - u1) * 66 + u1;
    const float* pe1 = s_emit0  + (1 - u1) * 64 + (u1 - 1);
    const float* pb2 = s_blank0 + (0 - 64) * 66 + 64;
    const float* pe2 = s_emit0  + (1 - 64) * 64 + 63;

    // Diagonal d = 0: only cell (0,0) = 0.
    float p0 = (lane == 0) ? 0.0f : NEG;
    float p1 = NEG, p2 = NEG;

    const int src = (lane + 31) & 31;
    const bool l0 = (lane == 0);

    // Prologue prefetch: values for d = 1.
    float blk0 = *pb0; pb0 += 66;
    float emt0 = *pe0; pe0 += 64;
    float blk1 = *pb1; pb1 += 66;
    float emt1 = *pe1; pe1 += 64;
    float blk2 = *pb2; pb2 += 66;
    float emt2 = *pe2; pe2 += 64;

    for (int d = 1; d <= d_end; d++) {
        float s0 = __shfl_sync(0xffffffffu, p0, src);
        float s1 = __shfl_sync(0xffffffffu, p1, src);

        // Prefetch diagonal d+1 (independent of this iteration's chain).
        float blk0n = *pb0; pb0 += 66;
        float emt0n = *pe0; pe0 += 64;
        float blk1n = *pb1; pb1 += 66;
        float emt1n = *pe1; pe1 += 64;
        float blk2n = *pb2; pb2 += 66;
        float emt2n = *pe2; pe2 += 64;

        float nb0 = l0 ? NEG : s0;       // u=0 has no left neighbor
        float nb1 = l0 ? s0  : s1;       // u1=32's left neighbor = lane31 slot0
        float nb2 = p1;                  // u=64's left neighbor = own slot1 (lane31)

        p0 = lae2(p0 + blk0, nb0 + emt0);
        p1 = lae2(p1 + blk1, nb1 + emt1);
        p2 = lae2(p2 + blk2, nb2 + emt2);

        blk0 = blk0n; emt0 = emt0n;
        blk1 = blk1n; emt1 = emt1n;
        blk2 = blk2n; emt2 = emt2n;
    }

    // Extract alpha[t_last][u_last] from the final diagonal.
    float af;
    if (u_last == 64)      af = __shfl_sync(0xffffffffu, p2, 31);
    else if (u_last >= 32) af = __shfl_sync(0xffffffffu, p1, u_last - 32);
    else                   af = __shfl_sync(0xffffffffu, p0, u_last);

    if (lane == 0) {
        out[b] = -(af + s_blank0[t_last * 66 + u_last]) * LN2;
    }
}

// ---------------------------------------------------------------------------
extern "C" void kernel_launch(void* const* d_in, const int* in_sizes, int n_in,
                              void* d_out, int out_size)
{
    const float* logits         = (const float*)d_in[0];
    const int*   targets        = (const int*)  d_in[1];
    const int*   logit_lengths  = (const int*)  d_in[2];
    const int*   target_lengths = (const int*)  d_in[3];
    float*       out            = (float*)      d_out;

    const int smem_bytes = TOT_F * (int)sizeof(float);
    static int attr_set = 0;
    if (!attr_set) {
        cudaFuncSetAttribute(dp_kernel, cudaFuncAttributeMaxDynamicSharedMemorySize, smem_bytes);
        attr_set = 1;
    }

    int rows   = Bn * Tn * U1n;            // 66560 rows -> one warp each
    int blocks = (rows * 32 + 255) / 256;  // 8320 blocks

    lse_kernel<<<blocks, 256>>>(logits, targets, logit_lengths, target_lengths);
    dp_kernel<<<Bn, 128, smem_bytes>>>(logit_lengths, target_lengths, out);
}

// round 10
// speedup vs baseline: 3.2403x; 1.1608x over previous
#include <cuda_runtime.h>
#include <cstdint>
#include <cstddef>

// Problem constants (fixed by the dataset)
#define Bn   8
#define Tn   128
#define Un   64
#define U1n  65          // U+1
#define Vn   1024
// blank = V-1 (last class)

#define LOG2E 1.4426950408889634f
#define LN2   0.6931471805599453f

// Scratch (BASE-2 log domain). g_blank stored PADDED to stride 66 so the DP
// preload is a flat vectorized copy.
__device__ __align__(16) float g_blank[Bn * Tn * 66];  // lp2[..., blank]
__device__ __align__(16) float g_emit [Bn * Tn * Un];  // lp2[..., targets[b,u]]

__device__ __forceinline__ float neg_inf() { return __int_as_float(0xff800000u); }

// Base-2 logaddexp via EX2 + degree-5 minimax poly for log2(1+y), y in [0,1].
// (A&S 4.1.43 coeffs x log2e, |err| <= 1.5e-5.)  P(0)=0, so:
//   both -inf: z clamps to -45 -> y~3e-14 -> g~4e-14 -> mx+g = -inf (no NaN).
//   one  -inf: g ~ 0 -> returns finite max.
// Only ONE MUFU (EX2) per call -> 3 MUFUs/diagonal instead of 6.
__device__ __forceinline__ float lae2p(float va, float vb) {
    const float C1 =  1.4419672f;
    const float C2 = -0.7096747f;
    const float C3 =  0.4176170f;
    const float C4 = -0.1962970f;
    const float C5 =  0.0463940f;
    float mx = fmaxf(va, vb);
    float mn = fminf(va, vb);
    float z  = fmaxf(mn - mx, -45.0f);
    float y;
    asm("ex2.approx.ftz.f32 %0, %1;" : "=f"(y) : "f"(z));
    float g = y * (C1 + y * (C2 + y * (C3 + y * (C4 + y * C5))));
    return mx + g;
}

// ---------------------------------------------------------------------------
// Kernel 1: per-row log-sum-exp over V=1024; one warp per (b,t,u) row.
// Rows outside [0,T_l) x [0,U_l] skipped entirely (~43% DRAM saved); at the
// LTS/DRAM cap (~6.5 TB/s). Outputs scaled by log2(e); blank stored stride-66.
// ---------------------------------------------------------------------------
__global__ void __launch_bounds__(256) lse_kernel(
    const float* __restrict__ logits,
    const int*   __restrict__ targets,
    const int*   __restrict__ logit_lengths,
    const int*   __restrict__ target_lengths)
{
    int warp = (int)((blockIdx.x * 256u + threadIdx.x) >> 5);
    int lane = threadIdx.x & 31;
    if (warp >= Bn * Tn * U1n) return;

    int b   = warp / (Tn * U1n);
    int rem = warp - b * (Tn * U1n);
    int t   = rem / U1n;
    int u   = rem - t * U1n;

    int Tl = logit_lengths[b];
    int Ul = target_lengths[b];
    if (t >= Tl || u > Ul) return;   // never read by the DP

    const float4* row = reinterpret_cast<const float4*>(logits) + (size_t)warp * (Vn / 4);
    float4 v[8];
#pragma unroll
    for (int j = 0; j < 8; j++) v[j] = row[j * 32 + lane];

    float m = v[0].x;
#pragma unroll
    for (int j = 0; j < 8; j++) {
        m = fmaxf(m, v[j].x); m = fmaxf(m, v[j].y);
        m = fmaxf(m, v[j].z); m = fmaxf(m, v[j].w);
    }
    float s = 0.0f;
#pragma unroll
    for (int j = 0; j < 8; j++) {
        s += __expf(v[j].x - m); s += __expf(v[j].y - m);
        s += __expf(v[j].z - m); s += __expf(v[j].w - m);
    }

    // blank class = V-1: lives in v[7].w of lane 31; grab before reduction.
    float blankv = __shfl_sync(0xffffffffu, v[7].w, 31);

    // Butterfly combine of (m, s)
#pragma unroll
    for (int off = 16; off; off >>= 1) {
        float om = __shfl_xor_sync(0xffffffffu, m, off);
        float os = __shfl_xor_sync(0xffffffffu, s, off);
        float nm = fmaxf(m, om);
        s = s * __expf(m - nm) + os * __expf(om - nm);
        m = nm;
    }
    float lse = m + __logf(s);

    if (lane == 0) {
        g_blank[(b * Tn + t) * 66 + u] = (blankv - lse) * LOG2E;
        if (u < Ul) {
            int tgt = targets[b * Un + u];
            g_emit[(b * Tn + t) * Un + u] = (logits[(size_t)warp * Vn + tgt] - lse) * LOG2E;
        }
    }
}

// ---------------------------------------------------------------------------
// Kernel 2: anti-diagonal wavefront DP, one warp per batch, base-2 log domain.
// BLOCKED ownership: lane l owns u = 2l (slot0) and u = 2l+1 (slot1);
// u = 64 is slot2 (lane31's value is real: its left neighbor u=63 = own slot1).
//   slot1 (odd u): both parents local registers -> NO shfl on its chain.
//   slot0 (even u): left parent = lane l-1's slot1 -> 1 shfl/diagonal, which
//   the dataflow absorbs as a bounded lag (rate ~73 cyc/diag, not ~190).
// Boundary handling by construction (padded zero-filled SMEM, -inf regs);
// only lane0's "no left neighbor" needs one select.
// ---------------------------------------------------------------------------
#define PAD_LO   64
#define SROWS    256                    // rows -64..191
#define BLK_F    (SROWS * 66)           // 16896 floats
#define EMT_F    (SROWS * 64)           // 16384 floats
#define TAIL_F   64                     // pad for last prefetch
#define TOT_F    (BLK_F + EMT_F + TAIL_F)

__global__ void __launch_bounds__(128) dp_kernel(
    const int* __restrict__ logit_lengths,
    const int* __restrict__ target_lengths,
    float*     __restrict__ out)
{
    int b    = blockIdx.x;
    int tid  = threadIdx.x;
    int lane = tid & 31;
    int Tl   = logit_lengths[b];
    int Ul   = target_lengths[b];

    extern __shared__ float sh[];
    float* s_blank0 = sh + PAD_LO * 66;              // row-0 of blank
    float* s_emit0  = sh + BLK_F + PAD_LO * 64;      // row-0 of emit

    // Zero the whole padded region (vectorized).
    {
        float4* sh4 = reinterpret_cast<float4*>(sh);
        const float4 z4 = make_float4(0.f, 0.f, 0.f, 0.f);
        for (int i = tid; i < TOT_F / 4; i += 128) sh4[i] = z4;
    }
    __syncthreads();

    // Flat vectorized preload (layouts match exactly: stride 66 / 64).
    {
        const float2* gb2 = reinterpret_cast<const float2*>(g_blank + b * Tn * 66);
        float2* sb2 = reinterpret_cast<float2*>(s_blank0);
        int n2 = Tl * 33;
        for (int i = tid; i < n2; i += 128) sb2[i] = gb2[i];

        const float4* ge4 = reinterpret_cast<const float4*>(g_emit + b * Tn * Un);
        float4* se4 = reinterpret_cast<float4*>(s_emit0);
        int n4 = Tl * 16;
        for (int i = tid; i < n4; i += 128) se4[i] = ge4[i];
    }
    __syncthreads();
    if (tid >= 32) return;               // warp 0 runs the DP alone

    const float NEG = neg_inf();
    const int u0 = 2 * lane;             // even column
    const int u1 = 2 * lane + 1;         // odd column
    const int t_last = Tl - 1;
    const int u_last = Ul;
    const int d_end  = t_last + u_last;

    // Incremental SMEM pointers, positioned for d = 1.
    const float* pb0 = s_blank0 + (0 - u0) * 66 + u0;          // row d-1-u0
    const float* pe0 = s_emit0  + (1 - u0) * 64 + (u0 - 1);    // row d-u0, col u0-1
    const float* pb1 = s_blank0 + (0 - u1) * 66 + u1;
    const float* pe1 = s_emit0  + (1 - u1) * 64 + (u1 - 1);
    const float* pb2 = s_blank0 + (0 - 64) * 66 + 64;
    const float* pe2 = s_emit0  + (1 - 64) * 64 + 63;

    // Diagonal d = 0: only cell (0,0) (= lane0 slot0) is 0.
    float p0 = (lane == 0) ? 0.0f : NEG;
    float p1 = NEG, p2 = NEG;

    const int src = (lane + 31) & 31;
    const bool l0 = (lane == 0);

    // Prologue prefetch: values for d = 1.
    float blk0 = *pb0; pb0 += 66;
    float emt0 = *pe0; pe0 += 64;
    float blk1 = *pb1; pb1 += 66;
    float emt1 = *pe1; pe1 += 64;
    float blk2 = *pb2; pb2 += 66;
    float emt2 = *pe2; pe2 += 64;

    for (int d = 1; d <= d_end; d++) {
        // Only the even slot needs a cross-lane value: lane l-1's odd alpha.
        float s1 = __shfl_sync(0xffffffffu, p1, src);

        // Prefetch diagonal d+1 (independent of this iteration's chain).
        float blk0n = *pb0; pb0 += 66;
        float emt0n = *pe0; pe0 += 64;
        float blk1n = *pb1; pb1 += 66;
        float emt1n = *pe1; pe1 += 64;
        float blk2n = *pb2; pb2 += 66;
        float emt2n = *pe2; pe2 += 64;

        float nb0 = l0 ? NEG : s1;       // u=0 has no left neighbor
        float nb1 = p0;                  // u1-1 = 2l = own slot0 (prev diag)
        float nb2 = p1;                  // u=64's left = u=63 = lane31 slot1

        float q0 = lae2p(p0 + blk0, nb0 + emt0);
        float q1 = lae2p(p1 + blk1, nb1 + emt1);
        float q2 = lae2p(p2 + blk2, nb2 + emt2);
        p0 = q0; p1 = q1; p2 = q2;

        blk0 = blk0n; emt0 = emt0n;
        blk1 = blk1n; emt1 = emt1n;
        blk2 = blk2n; emt2 = emt2n;
    }

    // Extract alpha[t_last][u_last] from the final diagonal.
    float af;
    if (u_last == 64)          af = __shfl_sync(0xffffffffu, p2, 31);
    else if (u_last & 1)       af = __shfl_sync(0xffffffffu, p1, u_last >> 1);
    else                       af = __shfl_sync(0xffffffffu, p0, u_last >> 1);

    if (lane == 0) {
        out[b] = -(af + s_blank0[t_last * 66 + u_last]) * LN2;
    }
}

// ---------------------------------------------------------------------------
extern "C" void kernel_launch(void* const* d_in, const int* in_sizes, int n_in,
                              void* d_out, int out_size)
{
    const float* logits         = (const float*)d_in[0];
    const int*   targets        = (const int*)  d_in[1];
    const int*   logit_lengths  = (const int*)  d_in[2];
    const int*   target_lengths = (const int*)  d_in[3];
    float*       out            = (float*)      d_out;

    const int smem_bytes = TOT_F * (int)sizeof(float);
    static int attr_set = 0;
    if (!attr_set) {
        cudaFuncSetAttribute(dp_kernel, cudaFuncAttributeMaxDynamicSharedMemorySize, smem_bytes);
        attr_set = 1;
    }

    int rows   = Bn * Tn * U1n;            // 66560 rows -> one warp each
    int blocks = (rows * 32 + 255) / 256;  // 8320 blocks

    lse_kernel<<<blocks, 256>>>(logits, targets, logit_lengths, target_lengths);
    dp_kernel<<<Bn, 128, smem_bytes>>>(logit_lengths, target_lengths, out);
}